// round 12
// baseline (speedup 1.0000x reference)
#include <cuda_runtime.h>
#include <cstdint>

// ResBlock_71021579207010 — fused binarized ResBlock (B=32, T=8192, C=F=128, K=2, dil=16).
//
// Algebra (verified R4/R5/R8/R10/R11, rel_err ~2e-7):
//   shortcut[b,t,f] = sum_c sign(x[b,t,c]) * sign(w_sc[0,c,f])           (exact binary dot)
//   conv2 input = ste_sign(relu(...)) == +1  =>  conv2 out constant per (t<16 | t>=16)
//   conv1/bn1/w1/beta1/mean1/var1 are dead.
//   out = relu( shortcut + relu(bn2(const)) )
//
// Measured landscape: main loop is pinned at ~5.8 TB/s combined r+w regardless of
// schedule (R5 45.7 / R8 45.9 / R10 46.1); raising occupancy HURT (R11: 49.8).
// => R12 returns to the proven-fastest R5 main kernel (2048 blocks, 4/SM, unroll 4,
// plain loads) and attacks the ~5.6us overhead instead: the precompute kernel is
// rebuilt as ONE 256-thread block with fully COALESCED loads (consecutive threads ->
// consecutive f) and a 2-way c-split combined in smem, replacing the old 128x32
// stride-512B version.

#define T_LEN   8192
#define C_DIM   128
#define F_DIM   128
#define B_DIM   32
#define ROWS_TOTAL (B_DIM * T_LEN)      // 262144

__device__ uint4 g_wsc[F_DIM];    // packed sign(w_sc): word k bit l <-> channel c = 4*l + k
__device__ float g_clo[F_DIM];    // 128 + relu(bn2(S1))       for t <  16
__device__ float g_chi[F_DIM];    // 128 + relu(bn2(S0+S1))    for t >= 16

// Single block, 256 threads: tid < 128 handles channels c in [0,64) for f = tid,
// tid >= 128 handles c in [64,128) for f = tid-128. All global loads are coalesced
// (consecutive threads read consecutive f). Halves combined through shared memory.
// Packing convention (matches main kernel ballots): word k = c%4, bit l = c/4.
__global__ void precompute_kernel(const float* __restrict__ w2,    // [2,128,128]
                                  const float* __restrict__ w_sc,  // [1,128,128]
                                  const float* __restrict__ beta2,
                                  const float* __restrict__ mean2,
                                  const float* __restrict__ var2) {
    __shared__ unsigned s_w[2][F_DIM][4];
    __shared__ int      s_n0[2][F_DIM];
    __shared__ int      s_n1[2][F_DIM];

    const int tid  = threadIdx.x;           // 0..255
    const int half = tid >> 7;              // 0 or 1
    const int f    = tid & 127;
    const int c0   = half * 64;

    unsigned w[4] = {0u, 0u, 0u, 0u};
    int n0 = 0, n1 = 0;

    #pragma unroll 16
    for (int j = 0; j < 64; ++j) {
        const int c = c0 + j;
        const float vs = w_sc[c * F_DIM + f];              // coalesced across f
        w[c & 3] |= (vs < 0.0f ? 1u : 0u) << (c >> 2);
        n0 += (w2[(0 * C_DIM + c) * F_DIM + f] < 0.0f);
        n1 += (w2[(1 * C_DIM + c) * F_DIM + f] < 0.0f);
    }

    s_w[half][f][0] = w[0];  s_w[half][f][1] = w[1];
    s_w[half][f][2] = w[2];  s_w[half][f][3] = w[3];
    s_n0[half][f] = n0;
    s_n1[half][f] = n1;
    __syncthreads();

    if (half == 0) {
        uint4 pw;
        pw.x = s_w[0][f][0] | s_w[1][f][0];
        pw.y = s_w[0][f][1] | s_w[1][f][1];
        pw.z = s_w[0][f][2] | s_w[1][f][2];
        pw.w = s_w[0][f][3] | s_w[1][f][3];
        g_wsc[f] = pw;

        const int m0 = s_n0[0][f] + s_n0[1][f];
        const int m1 = s_n1[0][f] + s_n1[1][f];
        const float S0 = (float)(C_DIM - 2 * m0);
        const float S1 = (float)(C_DIM - 2 * m1);
        const float inv = rsqrtf(var2[f] + 1e-3f);
        const float lo  = (S1      - mean2[f]) * inv + beta2[f];
        const float hi  = (S0 + S1 - mean2[f]) * inv + beta2[f];
        // pre-bias by +C_DIM: out = relu((C_DIM - 2*neq) + relu(bn)) = relu(fma(neq,-2,cst))
        g_clo[f] = fmaxf(lo, 0.0f) + (float)C_DIM;
        g_chi[f] = fmaxf(hi, 0.0f) + (float)C_DIM;
    }
}

#define BLOCK_THREADS 256
#define WARPS_PER_BLOCK (BLOCK_THREADS / 32)              // 8
#define ROWS_PER_WARP 16
#define ROWS_PER_BLOCK (WARPS_PER_BLOCK * ROWS_PER_WARP)  // 128
#define GRID_BLOCKS (ROWS_TOTAL / ROWS_PER_BLOCK)         // 2048

// Proven-fastest main kernel (R5 shape: 45.7us, DRAM 59%): register-hoisted weights,
// unroll-4 load batching, per-row constant select, plain cached loads/stores.
__global__ __launch_bounds__(BLOCK_THREADS)
void resblock_main_kernel(const float* __restrict__ x, float* __restrict__ out) {
    const int lane = threadIdx.x & 31;
    const int warp = threadIdx.x >> 5;
    const int base = blockIdx.x * ROWS_PER_BLOCK;

    // Per-thread weights/constants in registers (f = 4*lane+j is loop-invariant).
    const uint4* wp = (const uint4*)g_wsc + 4 * lane;
    const uint4 wb0 = wp[0];
    const uint4 wb1 = wp[1];
    const uint4 wb2 = wp[2];
    const uint4 wb3 = wp[3];
    const float4 chi = ((const float4*)g_chi)[lane];
    const float4 clo = ((const float4*)g_clo)[lane];

    #pragma unroll 4
    for (int i = 0; i < ROWS_PER_WARP; ++i) {
        // Consecutive warps take consecutive rows each iteration -> the block walks
        // contiguous 4 KiB chunks (fully coalesced 128B segments).
        const int r = base + i * WARPS_PER_BLOCK + warp;     // row = b*T + t
        const float4 v = *(const float4*)(x + (size_t)r * C_DIM + 4 * lane);

        // Packed sign bits of the x-row; ballot broadcasts each word to all lanes.
        // Word k bit l = sign(x[c = 4*l + k]) — matches the precompute packing.
        const unsigned a0 = __ballot_sync(0xffffffffu, v.x < 0.0f);
        const unsigned a1 = __ballot_sync(0xffffffffu, v.y < 0.0f);
        const unsigned a2 = __ballot_sync(0xffffffffu, v.z < 0.0f);
        const unsigned a3 = __ballot_sync(0xffffffffu, v.w < 0.0f);

        const bool hi = ((r & (T_LEN - 1)) >= 16);

        const int n0 = __popc(a0 ^ wb0.x) + __popc(a1 ^ wb0.y) + __popc(a2 ^ wb0.z) + __popc(a3 ^ wb0.w);
        const int n1 = __popc(a0 ^ wb1.x) + __popc(a1 ^ wb1.y) + __popc(a2 ^ wb1.z) + __popc(a3 ^ wb1.w);
        const int n2 = __popc(a0 ^ wb2.x) + __popc(a1 ^ wb2.y) + __popc(a2 ^ wb2.z) + __popc(a3 ^ wb2.w);
        const int n3 = __popc(a0 ^ wb3.x) + __popc(a1 ^ wb3.y) + __popc(a2 ^ wb3.z) + __popc(a3 ^ wb3.w);

        float4 o;
        o.x = fmaxf(fmaf((float)n0, -2.0f, hi ? chi.x : clo.x), 0.0f);
        o.y = fmaxf(fmaf((float)n1, -2.0f, hi ? chi.y : clo.y), 0.0f);
        o.z = fmaxf(fmaf((float)n2, -2.0f, hi ? chi.z : clo.z), 0.0f);
        o.w = fmaxf(fmaf((float)n3, -2.0f, hi ? chi.w : clo.w), 0.0f);

        *(float4*)(out + (size_t)r * F_DIM + 4 * lane) = o;
    }
}

extern "C" void kernel_launch(void* const* d_in, const int* in_sizes, int n_in,
                              void* d_out, int out_size) {
    // metadata order: x, w1, w2, w_sc, beta1, mean1, var1, beta2, mean2, var2
    const float* x     = (const float*)d_in[0];
    const float* w2    = (const float*)d_in[2];
    const float* w_sc  = (const float*)d_in[3];
    const float* beta2 = (const float*)d_in[7];
    const float* mean2 = (const float*)d_in[8];
    const float* var2  = (const float*)d_in[9];
    float* out = (float*)d_out;

    precompute_kernel<<<1, 256>>>(w2, w_sc, beta2, mean2, var2);
    resblock_main_kernel<<<GRID_BLOCKS, BLOCK_THREADS>>>(x, out);
}

// round 14
// speedup vs baseline: 1.3573x; 1.3573x over previous
#include <cuda_runtime.h>
#include <cstdint>

// ResBlock_71021579207010 — fused binarized ResBlock (B=32, T=8192, C=F=128, K=2, dil=16).
//
// Algebra (verified across R4..R12, rel_err ~2e-7):
//   shortcut[b,t,f] = sum_c sign(x[b,t,c]) * sign(w_sc[0,c,f])           (exact binary dot)
//   conv2 input = ste_sign(relu(...)) == +1  =>  conv2 out constant per (t<16 | t>=16)
//   conv1/bn1/w1/beta1/mean1/var1 are dead.
//   out = relu( shortcut + relu(bn2(const)) )
//
// R13 vs R12: main kernel unchanged (44.5us, best measured). The R12 single-block
// precompute cost ~25us (one SM, latency-serialized). Rebuilt for MINIMUM LATENCY:
// 128 blocks (one per f) x 128 threads; warp w lane l owns channel c = 4l + w, so a
// single warp ballot of (w_sc[c]<0) IS word w of the main kernel's packing. Only 3
// independent LDGs per thread -> critical path ~ one DRAM round-trip (~0.5us chip-wide).

#define T_LEN   8192
#define C_DIM   128
#define F_DIM   128
#define B_DIM   32
#define ROWS_TOTAL (B_DIM * T_LEN)      // 262144

__device__ uint4 g_wsc[F_DIM];    // packed sign(w_sc): word k bit l <-> channel c = 4*l + k
__device__ float g_clo[F_DIM];    // 128 + relu(bn2(S1))       for t <  16
__device__ float g_chi[F_DIM];    // 128 + relu(bn2(S0+S1))    for t >= 16

__global__ void precompute_kernel(const float* __restrict__ w2,    // [2,128,128]
                                  const float* __restrict__ w_sc,  // [1,128,128]
                                  const float* __restrict__ beta2,
                                  const float* __restrict__ mean2,
                                  const float* __restrict__ var2) {
    const int f = blockIdx.x;            // 0..127
    const int w = threadIdx.x >> 5;      // warp 0..3  -> packed word index
    const int l = threadIdx.x & 31;      // lane       -> bit index
    const int c = 4 * l + w;             // channel owned by this thread

    __shared__ unsigned s_w[4];
    __shared__ int s_n0[4], s_n1[4];

    // Three independent loads, issued back-to-back (latency fully overlapped).
    const float vs = w_sc[c * F_DIM + f];
    const float v0 = w2[(0 * C_DIM + c) * F_DIM + f];
    const float v1 = w2[(1 * C_DIM + c) * F_DIM + f];

    // Warp w's ballot over c = 4l + w IS packed word w (bit l <-> c = 4l + w).
    const unsigned pw = __ballot_sync(0xffffffffu, vs < 0.0f);
    const unsigned b0 = __ballot_sync(0xffffffffu, v0 < 0.0f);
    const unsigned b1 = __ballot_sync(0xffffffffu, v1 < 0.0f);

    if (l == 0) {
        s_w[w]  = pw;
        s_n0[w] = __popc(b0);
        s_n1[w] = __popc(b1);
    }
    __syncthreads();

    if (threadIdx.x == 0) {
        g_wsc[f] = make_uint4(s_w[0], s_w[1], s_w[2], s_w[3]);

        const int n0 = s_n0[0] + s_n0[1] + s_n0[2] + s_n0[3];   // negatives in w2[0,:,f]
        const int n1 = s_n1[0] + s_n1[1] + s_n1[2] + s_n1[3];   // negatives in w2[1,:,f]
        const float S0 = (float)(C_DIM - 2 * n0);
        const float S1 = (float)(C_DIM - 2 * n1);
        const float inv = rsqrtf(var2[f] + 1e-3f);
        const float lo  = (S1      - mean2[f]) * inv + beta2[f];
        const float hi  = (S0 + S1 - mean2[f]) * inv + beta2[f];
        // pre-bias by +C_DIM: out = relu((C_DIM - 2*neq) + relu(bn)) = relu(fma(neq,-2,cst))
        g_clo[f] = fmaxf(lo, 0.0f) + (float)C_DIM;
        g_chi[f] = fmaxf(hi, 0.0f) + (float)C_DIM;
    }
}

#define BLOCK_THREADS 256
#define WARPS_PER_BLOCK (BLOCK_THREADS / 32)              // 8
#define ROWS_PER_WARP 16
#define ROWS_PER_BLOCK (WARPS_PER_BLOCK * ROWS_PER_WARP)  // 128
#define GRID_BLOCKS (ROWS_TOTAL / ROWS_PER_BLOCK)         // 2048

// Proven-fastest main kernel (R5/R12 shape: 44.5us): register-hoisted weights,
// unroll-4 load batching, per-row constant select, plain cached loads/stores.
__global__ __launch_bounds__(BLOCK_THREADS)
void resblock_main_kernel(const float* __restrict__ x, float* __restrict__ out) {
    const int lane = threadIdx.x & 31;
    const int warp = threadIdx.x >> 5;
    const int base = blockIdx.x * ROWS_PER_BLOCK;

    // Per-thread weights/constants in registers (f = 4*lane+j is loop-invariant).
    const uint4* wp = (const uint4*)g_wsc + 4 * lane;
    const uint4 wb0 = wp[0];
    const uint4 wb1 = wp[1];
    const uint4 wb2 = wp[2];
    const uint4 wb3 = wp[3];
    const float4 chi = ((const float4*)g_chi)[lane];
    const float4 clo = ((const float4*)g_clo)[lane];

    #pragma unroll 4
    for (int i = 0; i < ROWS_PER_WARP; ++i) {
        // Consecutive warps take consecutive rows each iteration -> the block walks
        // contiguous 4 KiB chunks (fully coalesced 128B segments).
        const int r = base + i * WARPS_PER_BLOCK + warp;     // row = b*T + t
        const float4 v = *(const float4*)(x + (size_t)r * C_DIM + 4 * lane);

        // Packed sign bits of the x-row; ballot broadcasts each word to all lanes.
        // Word k bit l = sign(x[c = 4*l + k]) — matches the precompute packing.
        const unsigned a0 = __ballot_sync(0xffffffffu, v.x < 0.0f);
        const unsigned a1 = __ballot_sync(0xffffffffu, v.y < 0.0f);
        const unsigned a2 = __ballot_sync(0xffffffffu, v.z < 0.0f);
        const unsigned a3 = __ballot_sync(0xffffffffu, v.w < 0.0f);

        const bool hi = ((r & (T_LEN - 1)) >= 16);

        const int n0 = __popc(a0 ^ wb0.x) + __popc(a1 ^ wb0.y) + __popc(a2 ^ wb0.z) + __popc(a3 ^ wb0.w);
        const int n1 = __popc(a0 ^ wb1.x) + __popc(a1 ^ wb1.y) + __popc(a2 ^ wb1.z) + __popc(a3 ^ wb1.w);
        const int n2 = __popc(a0 ^ wb2.x) + __popc(a1 ^ wb2.y) + __popc(a2 ^ wb2.z) + __popc(a3 ^ wb2.w);
        const int n3 = __popc(a0 ^ wb3.x) + __popc(a1 ^ wb3.y) + __popc(a2 ^ wb3.z) + __popc(a3 ^ wb3.w);

        float4 o;
        o.x = fmaxf(fmaf((float)n0, -2.0f, hi ? chi.x : clo.x), 0.0f);
        o.y = fmaxf(fmaf((float)n1, -2.0f, hi ? chi.y : clo.y), 0.0f);
        o.z = fmaxf(fmaf((float)n2, -2.0f, hi ? chi.z : clo.z), 0.0f);
        o.w = fmaxf(fmaf((float)n3, -2.0f, hi ? chi.w : clo.w), 0.0f);

        *(float4*)(out + (size_t)r * F_DIM + 4 * lane) = o;
    }
}

extern "C" void kernel_launch(void* const* d_in, const int* in_sizes, int n_in,
                              void* d_out, int out_size) {
    // metadata order: x, w1, w2, w_sc, beta1, mean1, var1, beta2, mean2, var2
    const float* x     = (const float*)d_in[0];
    const float* w2    = (const float*)d_in[2];
    const float* w_sc  = (const float*)d_in[3];
    const float* beta2 = (const float*)d_in[7];
    const float* mean2 = (const float*)d_in[8];
    const float* var2  = (const float*)d_in[9];
    float* out = (float*)d_out;

    precompute_kernel<<<F_DIM, 128>>>(w2, w_sc, beta2, mean2, var2);
    resblock_main_kernel<<<GRID_BLOCKS, BLOCK_THREADS>>>(x, out);
}